// round 5
// baseline (speedup 1.0000x reference)
#include <cuda_runtime.h>
#include <math.h>

#define N_NODES 200000
#define N_EDGES 1000000
#define HDIM    64
#define NGRAPH  512
#define NCLS    10
#define BN_EPS  1e-5f

// ---------------- static device scratch (no allocation allowed) ----------------
__device__ __align__(256) float  g_buf1[(size_t)N_NODES * HDIM]; // h (gemm out) / final
__device__ __align__(256) float  g_buf2[(size_t)N_NODES * HDIM]; // agg
__device__ __align__(256) float  g_buf3[(size_t)N_NODES * HDIM]; // layer-1 output (residual)
__device__ __align__(256) float  g_deg [N_NODES];
__device__ __align__(256) float  g_dinv[N_NODES];
__device__ __align__(16)  double g_sums[2 * HDIM];
__device__ __align__(16)  float  g_scale[HDIM];
__device__ __align__(16)  float  g_shift[HDIM];
__device__ __align__(256) float  g_pooled[NGRAPH * HDIM];

// ---------------- degree / norm ----------------
__global__ void deg_init_kernel(float* __restrict__ deg) {
    int i = blockIdx.x * blockDim.x + threadIdx.x;
    if (i < N_NODES) deg[i] = 1.0f;   // self-loop
}

__global__ void deg_edges_kernel(const int* __restrict__ dst, float* __restrict__ deg) {
    int e = blockIdx.x * blockDim.x + threadIdx.x;
    if (e < N_EDGES) atomicAdd(&deg[dst[e]], 1.0f);
}

__global__ void dinv_kernel(const float* __restrict__ deg, float* __restrict__ dinv) {
    int i = blockIdx.x * blockDim.x + threadIdx.x;
    if (i < N_NODES) dinv[i] = rsqrtf(deg[i]);   // deg >= 1 always
}

// ---------------- 64x64 GEMM, fused self-loop epilogue ----------------
// block: 256 threads (tx=0..63 cols, ty=0..3), 64 rows per block.
__global__ void gemm64_kernel(const float* __restrict__ X, const float* __restrict__ W,
                              const float* __restrict__ dinv,
                              float* __restrict__ H, float* __restrict__ AGG) {
    __shared__ float Ws[64 * 64];
    __shared__ float Xs[64 * 65];  // pad to kill bank conflicts
    __shared__ float Ds[64];

    int tid  = threadIdx.x;
    int row0 = blockIdx.x * 64;

#pragma unroll
    for (int j = 0; j < 16; j++) Ws[tid + j * 256] = W[tid + j * 256];
#pragma unroll
    for (int j = 0; j < 16; j++) {
        int idx = tid + j * 256;
        Xs[(idx >> 6) * 65 + (idx & 63)] = X[(size_t)row0 * 64 + idx];
    }
    if (tid < 64) Ds[tid] = dinv[row0 + tid];
    __syncthreads();

    int tx = tid & 63;
    int ty = tid >> 6;
    float acc[16];
#pragma unroll
    for (int i = 0; i < 16; i++) acc[i] = 0.0f;

#pragma unroll
    for (int k = 0; k < 64; k++) {
        float w = Ws[k * 64 + tx];
#pragma unroll
        for (int i = 0; i < 16; i++)
            acc[i] += Xs[(ty + 4 * i) * 65 + k] * w;
    }

#pragma unroll
    for (int i = 0; i < 16; i++) {
        int r = ty + 4 * i;
        float d = Ds[r];
        size_t o = (size_t)(row0 + r) * 64 + tx;
        H[o]   = acc[i];
        AGG[o] = acc[i] * d * d;   // self-loop message, norm = dinv^2
    }
}

// ---------------- edge scatter: 16 threads/edge, float4 + vector red ----------------
__global__ void edge_agg_kernel(const int* __restrict__ src, const int* __restrict__ dst,
                                const float* __restrict__ dinv, const float* __restrict__ H,
                                float* __restrict__ AGG) {
    long long t = (long long)blockIdx.x * blockDim.x + threadIdx.x;
    int e = (int)(t >> 4);
    if (e >= N_EDGES) return;
    int part = (int)(t & 15);

    int s = __ldg(src + e);
    int d = __ldg(dst + e);
    float nm = __ldg(dinv + s) * __ldg(dinv + d);

    float4 v = __ldg((const float4*)(H + (size_t)s * 64) + part);
    float* out = AGG + (size_t)d * 64 + part * 4;
    asm volatile("red.global.add.v4.f32 [%0], {%1, %2, %3, %4};" ::
                 "l"(out), "f"(v.x * nm), "f"(v.y * nm), "f"(v.z * nm), "f"(v.w * nm)
                 : "memory");
}

// ---------------- batch-norm ----------------
__global__ void zero_sums_kernel(double* __restrict__ sums) {
    if (threadIdx.x < 2 * HDIM) sums[threadIdx.x] = 0.0;
}

// grid-stride stats over (agg + b); 256 threads = 4 row-lanes x 64 features
__global__ void bn_stats_kernel(const float* __restrict__ AGG, const float* __restrict__ b,
                                double* __restrict__ sums) {
    int f = threadIdx.x & 63;
    int grp = threadIdx.x >> 6;
    float bf = __ldg(b + f);
    float s = 0.0f, sq = 0.0f;
    for (int r = blockIdx.x * 4 + grp; r < N_NODES; r += gridDim.x * 4) {
        float v = AGG[(size_t)r * 64 + f] + bf;
        s += v;
        sq += v * v;
    }
    __shared__ float sh0[256];
    __shared__ float sh1[256];
    sh0[threadIdx.x] = s;
    sh1[threadIdx.x] = sq;
    __syncthreads();
    if (grp == 0) {
        s  = sh0[f] + sh0[f + 64] + sh0[f + 128] + sh0[f + 192];
        sq = sh1[f] + sh1[f + 64] + sh1[f + 128] + sh1[f + 192];
        atomicAdd(&sums[f], (double)s);
        atomicAdd(&sums[HDIM + f], (double)sq);
    }
}

// fold bias + BN into per-feature scale/shift:  out = relu(agg*scale + shift)
__global__ void bn_finalize_kernel(const double* __restrict__ sums,
                                   const float* __restrict__ b, const float* __restrict__ g,
                                   const float* __restrict__ be,
                                   float* __restrict__ scale, float* __restrict__ shift) {
    int f = threadIdx.x;
    if (f >= HDIM) return;
    double mean = sums[f] / (double)N_NODES;
    double var  = sums[HDIM + f] / (double)N_NODES - mean * mean;
    float rs = rsqrtf((float)var + BN_EPS);
    float sc = rs * g[f];
    scale[f] = sc;
    shift[f] = (float)((double)b[f] - mean) * sc + be[f];
}

// streaming float4 apply; prev==nullptr for layer 1, residual add for layer 2
__global__ void bn_apply_kernel(const float* __restrict__ AGG,
                                const float* __restrict__ scale, const float* __restrict__ shift,
                                const float* __restrict__ prev, float* __restrict__ OUT) {
    size_t i = (size_t)blockIdx.x * blockDim.x + threadIdx.x;   // float4 index
    if (i >= (size_t)N_NODES * 16) return;
    int f4 = (int)(i & 15);
    float4 a  = __ldg((const float4*)AGG + i);
    float4 sc = __ldg((const float4*)scale + f4);
    float4 sh = __ldg((const float4*)shift + f4);
    float4 o;
    o.x = fmaxf(fmaf(a.x, sc.x, sh.x), 0.0f);
    o.y = fmaxf(fmaf(a.y, sc.y, sh.y), 0.0f);
    o.z = fmaxf(fmaf(a.z, sc.z, sh.z), 0.0f);
    o.w = fmaxf(fmaf(a.w, sc.w, sh.w), 0.0f);
    if (prev != nullptr) {
        float4 p = __ldg((const float4*)prev + i);
        o.x += p.x; o.y += p.y; o.z += p.z; o.w += p.w;
    }
    ((float4*)OUT)[i] = o;
}

// ---------------- global mean pool (batch is sorted -> binary search, no atomics) ----------------
__global__ void pool_kernel(const float* __restrict__ HF, const int* __restrict__ batch,
                            float* __restrict__ pooled) {
    int g = blockIdx.x;
    __shared__ int s_start, s_end;
    if (threadIdx.x == 0) {
        int lo = 0, hi = N_NODES;
        while (lo < hi) { int mid = (lo + hi) >> 1; if (batch[mid] < g) lo = mid + 1; else hi = mid; }
        s_start = lo;
        hi = N_NODES;
        while (lo < hi) { int mid = (lo + hi) >> 1; if (batch[mid] < g + 1) lo = mid + 1; else hi = mid; }
        s_end = lo;
    }
    __syncthreads();
    int start = s_start, end = s_end;
    int f = threadIdx.x & 63;
    int grp = threadIdx.x >> 6;
    float s = 0.0f;
    for (int r = start + grp; r < end; r += 4)
        s += HF[(size_t)r * 64 + f];
    __shared__ float sh[256];
    sh[threadIdx.x] = s;
    __syncthreads();
    if (grp == 0) {
        s = sh[f] + sh[f + 64] + sh[f + 128] + sh[f + 192];
        int cnt = end - start;
        pooled[g * 64 + f] = s / (float)(cnt > 0 ? cnt : 1);
    }
}

// ---------------- MLP head + log_softmax (one block per graph) ----------------
__global__ void head_kernel(const float* __restrict__ pooled,
                            const float* __restrict__ lw1, const float* __restrict__ lb1,
                            const float* __restrict__ lw2, const float* __restrict__ lb2,
                            float* __restrict__ out) {
    int g = blockIdx.x;
    int t = threadIdx.x;
    __shared__ float p[64];
    __shared__ float z[32];
    __shared__ float lg[NCLS];
    p[t] = pooled[g * 64 + t];
    __syncthreads();
    if (t < 32) {
        float acc = lb1[t];
#pragma unroll
        for (int k = 0; k < 64; k++) acc += p[k] * lw1[k * 32 + t];
        z[t] = fmaxf(acc, 0.0f);
    }
    __syncthreads();
    if (t < NCLS) {
        float acc = lb2[t];
#pragma unroll
        for (int k = 0; k < 32; k++) acc += z[k] * lw2[k * 10 + t];
        lg[t] = acc;
    }
    __syncthreads();
    if (t == 0) {
        float m = lg[0];
#pragma unroll
        for (int c = 1; c < NCLS; c++) m = fmaxf(m, lg[c]);
        float se = 0.0f;
#pragma unroll
        for (int c = 0; c < NCLS; c++) se += expf(lg[c] - m);
        float l = m + logf(se);
#pragma unroll
        for (int c = 0; c < NCLS; c++) out[g * NCLS + c] = lg[c] - l;
    }
}

// ---------------- host ----------------
extern "C" void kernel_launch(void* const* d_in, const int* in_sizes, int n_in,
                              void* d_out, int out_size) {
    const float* x     = (const float*)d_in[0];
    const int*   ei    = (const int*)  d_in[1];
    const int*   batch = (const int*)  d_in[2];
    const float* W1  = (const float*)d_in[3];
    const float* b1  = (const float*)d_in[4];
    const float* g1  = (const float*)d_in[5];
    const float* be1 = (const float*)d_in[6];
    const float* W2  = (const float*)d_in[7];
    const float* b2  = (const float*)d_in[8];
    const float* g2  = (const float*)d_in[9];
    const float* be2 = (const float*)d_in[10];
    const float* lw1 = (const float*)d_in[11];
    const float* lb1 = (const float*)d_in[12];
    const float* lw2 = (const float*)d_in[13];
    const float* lb2 = (const float*)d_in[14];

    const int* src = ei;
    const int* dst = ei + N_EDGES;

    float *buf1, *buf2, *buf3, *deg, *dinv, *scale, *shift, *pooled;
    double* sums;
    cudaGetSymbolAddress((void**)&buf1,  g_buf1);
    cudaGetSymbolAddress((void**)&buf2,  g_buf2);
    cudaGetSymbolAddress((void**)&buf3,  g_buf3);
    cudaGetSymbolAddress((void**)&deg,   g_deg);
    cudaGetSymbolAddress((void**)&dinv,  g_dinv);
    cudaGetSymbolAddress((void**)&sums,  g_sums);
    cudaGetSymbolAddress((void**)&scale, g_scale);
    cudaGetSymbolAddress((void**)&shift, g_shift);
    cudaGetSymbolAddress((void**)&pooled,g_pooled);

    const int TB = 256;
    const int n_blk   = (N_NODES + TB - 1) / TB;
    const int e_blk   = (N_EDGES + TB - 1) / TB;
    const int ea_blk  = (int)(((long long)N_EDGES * 16 + TB - 1) / TB);
    const int app_blk = (int)(((long long)N_NODES * 16 + TB - 1) / TB);
    const int gemm_blk = N_NODES / 64;   // 200000 / 64 = 3125 exact

    // degrees / symmetric norm
    deg_init_kernel <<<n_blk, TB>>>(deg);
    deg_edges_kernel<<<e_blk, TB>>>(dst, deg);
    dinv_kernel     <<<n_blk, TB>>>(deg, dinv);

    // ---- layer 1 ----
    zero_sums_kernel<<<1, 128>>>(sums);
    gemm64_kernel   <<<gemm_blk, TB>>>(x, W1, dinv, buf1, buf2);
    edge_agg_kernel <<<ea_blk, TB>>>(src, dst, dinv, buf1, buf2);
    bn_stats_kernel <<<512, TB>>>(buf2, b1, sums);
    bn_finalize_kernel<<<1, 64>>>(sums, b1, g1, be1, scale, shift);
    bn_apply_kernel <<<app_blk, TB>>>(buf2, scale, shift, nullptr, buf3);

    // ---- layer 2 (+ residual) ----
    zero_sums_kernel<<<1, 128>>>(sums);
    gemm64_kernel   <<<gemm_blk, TB>>>(buf3, W2, dinv, buf1, buf2);
    edge_agg_kernel <<<ea_blk, TB>>>(src, dst, dinv, buf1, buf2);
    bn_stats_kernel <<<512, TB>>>(buf2, b2, sums);
    bn_finalize_kernel<<<1, 64>>>(sums, b2, g2, be2, scale, shift);
    bn_apply_kernel <<<app_blk, TB>>>(buf2, scale, shift, buf3, buf1);

    // ---- pool + head ----
    pool_kernel<<<NGRAPH, TB>>>(buf1, batch, pooled);
    head_kernel<<<NGRAPH, 64>>>(pooled, lw1, lb1, lw2, lb2, (float*)d_out);
}

// round 6
// speedup vs baseline: 1.1707x; 1.1707x over previous
#include <cuda_runtime.h>
#include <math.h>

#define N_NODES 200000
#define N_EDGES 1000000
#define HDIM    64
#define NGRAPH  512
#define NCLS    10
#define BN_EPS  1e-5f

#define SCAN_CHUNK 1024
#define SCAN_BLKS  ((N_NODES + SCAN_CHUNK - 1) / SCAN_CHUNK)   // 196

// ---------------- static device scratch ----------------
__device__ __align__(256) float  g_buf1[(size_t)N_NODES * HDIM]; // h' = h*dinv
__device__ __align__(256) float  g_buf2[(size_t)N_NODES * HDIM]; // agg
__device__ __align__(256) float  g_buf3[(size_t)N_NODES * HDIM]; // relu1 out / residual
__device__ __align__(256) int    g_adj[N_EDGES];                 // src ids grouped by dst
__device__ __align__(256) int    g_cnt[N_NODES];                 // in-degree (no self)
__device__ __align__(256) int    g_rowst[N_NODES];               // CSR row start
__device__ __align__(256) int    g_cursor[N_NODES];
__device__ __align__(256) int    g_localex[N_NODES];             // scan temp
__device__ __align__(16)  int    g_blksum[256];
__device__ __align__(16)  int    g_blkpre[256];
__device__ __align__(256) float  g_dinv[N_NODES];
__device__ __align__(16)  double g_sums[4 * HDIM];               // L1: [0,128) L2: [128,256)
__device__ __align__(16)  float  g_scale[2 * HDIM];
__device__ __align__(16)  float  g_shift[2 * HDIM];
__device__ __align__(256) float  g_pooled[NGRAPH * HDIM];

// ---------------- init: zero counts + BN sums ----------------
__global__ void init_kernel(int* __restrict__ cnt, double* __restrict__ sums) {
    int i = blockIdx.x * blockDim.x + threadIdx.x;
    if (i < N_NODES) cnt[i] = 0;
    if (i < 4 * HDIM) sums[i] = 0.0;
}

__global__ void deg_count_kernel(const int* __restrict__ dst, int* __restrict__ cnt) {
    int e = blockIdx.x * blockDim.x + threadIdx.x;
    if (e < N_EDGES) atomicAdd(&cnt[dst[e]], 1);
}

// ---------------- 3-kernel exclusive scan over cnt ----------------
__global__ void scanA_kernel(const int* __restrict__ cnt, int* __restrict__ localex,
                             int* __restrict__ blksum) {
    __shared__ int sh[256];
    int b = blockIdx.x, t = threadIdx.x;
    int base = b * SCAN_CHUNK + t * 4;
    int v0 = (base + 0 < N_NODES) ? cnt[base + 0] : 0;
    int v1 = (base + 1 < N_NODES) ? cnt[base + 1] : 0;
    int v2 = (base + 2 < N_NODES) ? cnt[base + 2] : 0;
    int v3 = (base + 3 < N_NODES) ? cnt[base + 3] : 0;
    int s = v0 + v1 + v2 + v3;
    sh[t] = s;
    __syncthreads();
#pragma unroll
    for (int off = 1; off < 256; off <<= 1) {
        int x = (t >= off) ? sh[t - off] : 0;
        __syncthreads();
        sh[t] += x;
        __syncthreads();
    }
    int excl = sh[t] - s;
    if (t == 255) blksum[b] = sh[255];
    if (base + 0 < N_NODES) localex[base + 0] = excl;  excl += v0;
    if (base + 1 < N_NODES) localex[base + 1] = excl;  excl += v1;
    if (base + 2 < N_NODES) localex[base + 2] = excl;  excl += v2;
    if (base + 3 < N_NODES) localex[base + 3] = excl;
}

__global__ void scanB_kernel(const int* __restrict__ blksum, int* __restrict__ blkpre) {
    __shared__ int sh[256];
    int t = threadIdx.x;
    int v = (t < SCAN_BLKS) ? blksum[t] : 0;
    sh[t] = v;
    __syncthreads();
#pragma unroll
    for (int off = 1; off < 256; off <<= 1) {
        int x = (t >= off) ? sh[t - off] : 0;
        __syncthreads();
        sh[t] += x;
        __syncthreads();
    }
    blkpre[t] = sh[t] - v;   // exclusive
}

// finalize CSR offsets + cursor + dinv
__global__ void scanC_kernel(const int* __restrict__ localex, const int* __restrict__ blkpre,
                             const int* __restrict__ cnt,
                             int* __restrict__ rowst, int* __restrict__ cursor,
                             float* __restrict__ dinv) {
    int i = blockIdx.x * blockDim.x + threadIdx.x;
    if (i >= N_NODES) return;
    int r = localex[i] + blkpre[i >> 10];
    rowst[i] = r;
    cursor[i] = r;
    dinv[i] = rsqrtf((float)(cnt[i] + 1));   // +1 self-loop
}

__global__ void scatter_kernel(const int* __restrict__ src, const int* __restrict__ dst,
                               int* __restrict__ cursor, int* __restrict__ adj) {
    int e = blockIdx.x * blockDim.x + threadIdx.x;
    if (e >= N_EDGES) return;
    int d = dst[e];
    int pos = atomicAdd(&cursor[d], 1);
    adj[pos] = src[e];
}

// ---------------- 64x64 GEMM, writes h' = (x@W)*dinv ----------------
__global__ void gemm64_kernel(const float* __restrict__ X, const float* __restrict__ W,
                              const float* __restrict__ dinv, float* __restrict__ HP) {
    __shared__ float Ws[64 * 64];
    __shared__ float Xs[64 * 65];
    __shared__ float Ds[64];

    int tid  = threadIdx.x;
    int row0 = blockIdx.x * 64;

#pragma unroll
    for (int j = 0; j < 16; j++) Ws[tid + j * 256] = W[tid + j * 256];
#pragma unroll
    for (int j = 0; j < 16; j++) {
        int idx = tid + j * 256;
        Xs[(idx >> 6) * 65 + (idx & 63)] = X[(size_t)row0 * 64 + idx];
    }
    if (tid < 64) Ds[tid] = dinv[row0 + tid];
    __syncthreads();

    int tx = tid & 63;
    int ty = tid >> 6;
    float acc[16];
#pragma unroll
    for (int i = 0; i < 16; i++) acc[i] = 0.0f;

#pragma unroll
    for (int k = 0; k < 64; k++) {
        float w = Ws[k * 64 + tx];
#pragma unroll
        for (int i = 0; i < 16; i++)
            acc[i] += Xs[(ty + 4 * i) * 65 + k] * w;
    }

#pragma unroll
    for (int i = 0; i < 16; i++) {
        int r = ty + 4 * i;
        HP[(size_t)(row0 + r) * 64 + tx] = acc[i] * Ds[r];
    }
}

// ---------------- CSR gather aggregation (no atomics) ----------------
// agg[d] = dinv[d] * (h'[d] + sum_{s in N(d)} h'[s])
__global__ void agg_kernel(const int* __restrict__ rowst, const int* __restrict__ cnt,
                           const int* __restrict__ adj, const float* __restrict__ dinv,
                           const float* __restrict__ HP, float* __restrict__ AGG) {
    int t = blockIdx.x * blockDim.x + threadIdx.x;   // t < N_NODES*16
    int node = t >> 4;
    int part = t & 15;
    const float4* Hp = (const float4*)HP;

    float4 acc = __ldg(Hp + node * 16 + part);   // self h'[d]
    int beg = __ldg(rowst + node);
    int c   = __ldg(cnt + node);
    int j = 0;
    for (; j + 1 < c; j += 2) {
        int s0 = __ldg(adj + beg + j);
        int s1 = __ldg(adj + beg + j + 1);
        float4 a = __ldg(Hp + s0 * 16 + part);
        float4 b = __ldg(Hp + s1 * 16 + part);
        acc.x += a.x + b.x; acc.y += a.y + b.y;
        acc.z += a.z + b.z; acc.w += a.w + b.w;
    }
    if (j < c) {
        int s0 = __ldg(adj + beg + j);
        float4 a = __ldg(Hp + s0 * 16 + part);
        acc.x += a.x; acc.y += a.y; acc.z += a.z; acc.w += a.w;
    }
    float dd = __ldg(dinv + node);
    acc.x *= dd; acc.y *= dd; acc.z *= dd; acc.w *= dd;
    ((float4*)AGG)[node * 16 + part] = acc;
}

// ---------------- BN stats over raw agg (bias cancels in BN) ----------------
__global__ void bn_stats_kernel(const float* __restrict__ AGG, double* __restrict__ sums) {
    int f = threadIdx.x & 63;
    int grp = threadIdx.x >> 6;
    float s = 0.0f, sq = 0.0f;
    for (int r = blockIdx.x * 4 + grp; r < N_NODES; r += gridDim.x * 4) {
        float v = AGG[(size_t)r * 64 + f];
        s += v;
        sq += v * v;
    }
    __shared__ float sh0[256];
    __shared__ float sh1[256];
    sh0[threadIdx.x] = s;
    sh1[threadIdx.x] = sq;
    __syncthreads();
    if (grp == 0) {
        s  = sh0[f] + sh0[f + 64] + sh0[f + 128] + sh0[f + 192];
        sq = sh1[f] + sh1[f + 64] + sh1[f + 128] + sh1[f + 192];
        atomicAdd(&sums[f], (double)s);
        atomicAdd(&sums[HDIM + f], (double)sq);
    }
}

__global__ void bn_finalize_kernel(const double* __restrict__ sums,
                                   const float* __restrict__ g, const float* __restrict__ be,
                                   float* __restrict__ scale, float* __restrict__ shift) {
    int f = threadIdx.x;
    if (f >= HDIM) return;
    double mean = sums[f] / (double)N_NODES;
    double var  = sums[HDIM + f] / (double)N_NODES - mean * mean;
    float rs = rsqrtf((float)var + BN_EPS);
    float sc = rs * g[f];
    scale[f] = sc;
    shift[f] = (float)(-mean) * sc + be[f];
}

// layer-1 apply: buf3 = relu(agg*scale + shift)
__global__ void bn_apply_kernel(const float* __restrict__ AGG,
                                const float* __restrict__ scale, const float* __restrict__ shift,
                                float* __restrict__ OUT) {
    size_t i = (size_t)blockIdx.x * blockDim.x + threadIdx.x;
    if (i >= (size_t)N_NODES * 16) return;
    int f4 = (int)(i & 15);
    float4 a  = __ldg((const float4*)AGG + i);
    float4 sc = __ldg((const float4*)scale + f4);
    float4 sh = __ldg((const float4*)shift + f4);
    float4 o;
    o.x = fmaxf(fmaf(a.x, sc.x, sh.x), 0.0f);
    o.y = fmaxf(fmaf(a.y, sc.y, sh.y), 0.0f);
    o.z = fmaxf(fmaf(a.z, sc.z, sh.z), 0.0f);
    o.w = fmaxf(fmaf(a.w, sc.w, sh.w), 0.0f);
    ((float4*)OUT)[i] = o;
}

// ---------------- fused: layer-2 BN apply + residual + mean pool ----------------
__global__ void pool_fused_kernel(const float* __restrict__ AGG2, const float* __restrict__ prev,
                                  const float* __restrict__ scale, const float* __restrict__ shift,
                                  const int* __restrict__ batch, float* __restrict__ pooled) {
    int g = blockIdx.x;
    __shared__ int s_start, s_end;
    if (threadIdx.x == 0) {
        int lo = 0, hi = N_NODES;
        while (lo < hi) { int mid = (lo + hi) >> 1; if (batch[mid] < g) lo = mid + 1; else hi = mid; }
        s_start = lo;
        hi = N_NODES;
        while (lo < hi) { int mid = (lo + hi) >> 1; if (batch[mid] < g + 1) lo = mid + 1; else hi = mid; }
        s_end = lo;
    }
    __syncthreads();
    int start = s_start, end = s_end;
    int f = threadIdx.x & 63;
    int grp = threadIdx.x >> 6;
    float sc = __ldg(scale + f);
    float sh = __ldg(shift + f);
    float s = 0.0f;
    for (int r = start + grp; r < end; r += 4) {
        float a = AGG2[(size_t)r * 64 + f];
        float p = prev[(size_t)r * 64 + f];
        s += fmaxf(fmaf(a, sc, sh), 0.0f) + p;
    }
    __shared__ float shm[256];
    shm[threadIdx.x] = s;
    __syncthreads();
    if (grp == 0) {
        s = shm[f] + shm[f + 64] + shm[f + 128] + shm[f + 192];
        int cnt = end - start;
        pooled[g * 64 + f] = s / (float)(cnt > 0 ? cnt : 1);
    }
}

// ---------------- MLP head + log_softmax ----------------
__global__ void head_kernel(const float* __restrict__ pooled,
                            const float* __restrict__ lw1, const float* __restrict__ lb1,
                            const float* __restrict__ lw2, const float* __restrict__ lb2,
                            float* __restrict__ out) {
    int g = blockIdx.x;
    int t = threadIdx.x;
    __shared__ float p[64];
    __shared__ float z[32];
    __shared__ float lg[NCLS];
    p[t] = pooled[g * 64 + t];
    __syncthreads();
    if (t < 32) {
        float acc = lb1[t];
#pragma unroll
        for (int k = 0; k < 64; k++) acc += p[k] * lw1[k * 32 + t];
        z[t] = fmaxf(acc, 0.0f);
    }
    __syncthreads();
    if (t < NCLS) {
        float acc = lb2[t];
#pragma unroll
        for (int k = 0; k < 32; k++) acc += z[k] * lw2[k * 10 + t];
        lg[t] = acc;
    }
    __syncthreads();
    if (t == 0) {
        float m = lg[0];
#pragma unroll
        for (int c = 1; c < NCLS; c++) m = fmaxf(m, lg[c]);
        float se = 0.0f;
#pragma unroll
        for (int c = 0; c < NCLS; c++) se += expf(lg[c] - m);
        float l = m + logf(se);
#pragma unroll
        for (int c = 0; c < NCLS; c++) out[g * NCLS + c] = lg[c] - l;
    }
}

// ---------------- host ----------------
extern "C" void kernel_launch(void* const* d_in, const int* in_sizes, int n_in,
                              void* d_out, int out_size) {
    const float* x     = (const float*)d_in[0];
    const int*   ei    = (const int*)  d_in[1];
    const int*   batch = (const int*)  d_in[2];
    const float* W1  = (const float*)d_in[3];
    // b1 = d_in[4]  (cancels inside BatchNorm)
    const float* g1  = (const float*)d_in[5];
    const float* be1 = (const float*)d_in[6];
    const float* W2  = (const float*)d_in[7];
    // b2 = d_in[8]
    const float* g2  = (const float*)d_in[9];
    const float* be2 = (const float*)d_in[10];
    const float* lw1 = (const float*)d_in[11];
    const float* lb1 = (const float*)d_in[12];
    const float* lw2 = (const float*)d_in[13];
    const float* lb2 = (const float*)d_in[14];

    const int* src = ei;
    const int* dst = ei + N_EDGES;

    float *buf1, *buf2, *buf3, *dinv, *scale, *shift, *pooled;
    int *adj, *cnt, *rowst, *cursor, *localex, *blksum, *blkpre;
    double* sums;
    cudaGetSymbolAddress((void**)&buf1,   g_buf1);
    cudaGetSymbolAddress((void**)&buf2,   g_buf2);
    cudaGetSymbolAddress((void**)&buf3,   g_buf3);
    cudaGetSymbolAddress((void**)&adj,    g_adj);
    cudaGetSymbolAddress((void**)&cnt,    g_cnt);
    cudaGetSymbolAddress((void**)&rowst,  g_rowst);
    cudaGetSymbolAddress((void**)&cursor, g_cursor);
    cudaGetSymbolAddress((void**)&localex,g_localex);
    cudaGetSymbolAddress((void**)&blksum, g_blksum);
    cudaGetSymbolAddress((void**)&blkpre, g_blkpre);
    cudaGetSymbolAddress((void**)&dinv,   g_dinv);
    cudaGetSymbolAddress((void**)&sums,   g_sums);
    cudaGetSymbolAddress((void**)&scale,  g_scale);
    cudaGetSymbolAddress((void**)&shift,  g_shift);
    cudaGetSymbolAddress((void**)&pooled, g_pooled);

    const int TB = 256;
    const int n_blk    = (N_NODES + TB - 1) / TB;
    const int e_blk    = (N_EDGES + TB - 1) / TB;
    const int agg_blk  = N_NODES * 16 / TB;    // 12500 exact
    const int app_blk  = (int)(((long long)N_NODES * 16 + TB - 1) / TB);
    const int gemm_blk = N_NODES / 64;         // 3125 exact

    // ---- CSR build + norms (shared by both layers) ----
    init_kernel     <<<n_blk, TB>>>(cnt, sums);
    deg_count_kernel<<<e_blk, TB>>>(dst, cnt);
    scanA_kernel    <<<SCAN_BLKS, 256>>>(cnt, localex, blksum);
    scanB_kernel    <<<1, 256>>>(blksum, blkpre);
    scanC_kernel    <<<n_blk, TB>>>(localex, blkpre, cnt, rowst, cursor, dinv);
    scatter_kernel  <<<e_blk, TB>>>(src, dst, cursor, adj);

    // ---- layer 1 ----
    gemm64_kernel   <<<gemm_blk, TB>>>(x, W1, dinv, buf1);
    agg_kernel      <<<agg_blk, TB>>>(rowst, cnt, adj, dinv, buf1, buf2);
    bn_stats_kernel <<<512, TB>>>(buf2, sums);
    bn_finalize_kernel<<<1, 64>>>(sums, g1, be1, scale, shift);
    bn_apply_kernel <<<app_blk, TB>>>(buf2, scale, shift, buf3);

    // ---- layer 2 ----
    gemm64_kernel   <<<gemm_blk, TB>>>(buf3, W2, dinv, buf1);
    agg_kernel      <<<agg_blk, TB>>>(rowst, cnt, adj, dinv, buf1, buf2);
    bn_stats_kernel <<<512, TB>>>(buf2, sums + 2 * HDIM);
    bn_finalize_kernel<<<1, 64>>>(sums + 2 * HDIM, g2, be2, scale + HDIM, shift + HDIM);

    // ---- fused BN2-apply + residual + pool, then head ----
    pool_fused_kernel<<<NGRAPH, TB>>>(buf2, buf3, scale + HDIM, shift + HDIM, batch, pooled);
    head_kernel<<<NGRAPH, 64>>>(pooled, lw1, lb1, lw2, lb2, (float*)d_out);
}

// round 7
// speedup vs baseline: 1.2397x; 1.0589x over previous
#include <cuda_runtime.h>
#include <math.h>

#define N_NODES 200000
#define N_EDGES 1000000
#define HDIM    64
#define NGRAPH  512
#define NCLS    10
#define BN_EPS  1e-5f

#define SCAN_CHUNK 1024
#define SCAN_BLKS  ((N_NODES + SCAN_CHUNK - 1) / SCAN_CHUNK)   // 196
#define NBUCKET 64
#define PSUM_STRIDE (NBUCKET * 2 * HDIM)   // 8192 doubles per layer

// ---------------- static device scratch ----------------
__device__ __align__(256) float  g_buf1[(size_t)N_NODES * HDIM]; // h' (gemm out)
__device__ __align__(256) float  g_buf2[(size_t)N_NODES * HDIM]; // AGG layer 1
__device__ __align__(256) float  g_buf3[(size_t)N_NODES * HDIM]; // AGG layer 2
__device__ __align__(256) int    g_adj[N_EDGES];
__device__ __align__(256) int    g_cnt[N_NODES];
__device__ __align__(256) int    g_rowst[N_NODES];
__device__ __align__(256) int    g_cursor[N_NODES];
__device__ __align__(256) int    g_localex[N_NODES];
__device__ __align__(16)  int    g_blksum[256];
__device__ __align__(16)  int    g_blkpre[256];
__device__ __align__(256) float  g_dinv[N_NODES];
__device__ __align__(256) double g_psums[2 * PSUM_STRIDE];       // [layer][bucket][128]
__device__ __align__(16)  float  g_scale[2 * HDIM];
__device__ __align__(16)  float  g_shift[2 * HDIM];
__device__ __align__(256) float  g_pooled[NGRAPH * HDIM];

// ---------------- init: zero counts + stat partials ----------------
__global__ void init_kernel(int* __restrict__ cnt, double* __restrict__ psums) {
    int i = blockIdx.x * blockDim.x + threadIdx.x;
    if (i < N_NODES) cnt[i] = 0;
    if (i < 2 * PSUM_STRIDE) psums[i] = 0.0;
}

__global__ void deg_count_kernel(const int* __restrict__ dst, int* __restrict__ cnt) {
    int e = blockIdx.x * blockDim.x + threadIdx.x;
    if (e < N_EDGES) atomicAdd(&cnt[dst[e]], 1);
}

// ---------------- 3-kernel exclusive scan over cnt ----------------
__global__ void scanA_kernel(const int* __restrict__ cnt, int* __restrict__ localex,
                             int* __restrict__ blksum) {
    __shared__ int sh[256];
    int b = blockIdx.x, t = threadIdx.x;
    int base = b * SCAN_CHUNK + t * 4;
    int v0 = (base + 0 < N_NODES) ? cnt[base + 0] : 0;
    int v1 = (base + 1 < N_NODES) ? cnt[base + 1] : 0;
    int v2 = (base + 2 < N_NODES) ? cnt[base + 2] : 0;
    int v3 = (base + 3 < N_NODES) ? cnt[base + 3] : 0;
    int s = v0 + v1 + v2 + v3;
    sh[t] = s;
    __syncthreads();
#pragma unroll
    for (int off = 1; off < 256; off <<= 1) {
        int x = (t >= off) ? sh[t - off] : 0;
        __syncthreads();
        sh[t] += x;
        __syncthreads();
    }
    int excl = sh[t] - s;
    if (t == 255) blksum[b] = sh[255];
    if (base + 0 < N_NODES) localex[base + 0] = excl;  excl += v0;
    if (base + 1 < N_NODES) localex[base + 1] = excl;  excl += v1;
    if (base + 2 < N_NODES) localex[base + 2] = excl;  excl += v2;
    if (base + 3 < N_NODES) localex[base + 3] = excl;
}

__global__ void scanB_kernel(const int* __restrict__ blksum, int* __restrict__ blkpre) {
    __shared__ int sh[256];
    int t = threadIdx.x;
    int v = (t < SCAN_BLKS) ? blksum[t] : 0;
    sh[t] = v;
    __syncthreads();
#pragma unroll
    for (int off = 1; off < 256; off <<= 1) {
        int x = (t >= off) ? sh[t - off] : 0;
        __syncthreads();
        sh[t] += x;
        __syncthreads();
    }
    blkpre[t] = sh[t] - v;
}

__global__ void scanC_kernel(const int* __restrict__ localex, const int* __restrict__ blkpre,
                             const int* __restrict__ cnt,
                             int* __restrict__ rowst, int* __restrict__ cursor,
                             float* __restrict__ dinv) {
    int i = blockIdx.x * blockDim.x + threadIdx.x;
    if (i >= N_NODES) return;
    int r = localex[i] + blkpre[i >> 10];
    rowst[i] = r;
    cursor[i] = r;
    dinv[i] = rsqrtf((float)(cnt[i] + 1));
}

__global__ void scatter_kernel(const int* __restrict__ src, const int* __restrict__ dst,
                               int* __restrict__ cursor, int* __restrict__ adj) {
    int e = blockIdx.x * blockDim.x + threadIdx.x;
    if (e >= N_EDGES) return;
    int d = dst[e];
    int pos = atomicAdd(&cursor[d], 1);
    adj[pos] = src[e];
}

// ---------------- 64x64 GEMM; optional fused BN+relu on input load ----------------
template <bool APPLY_BN>
__global__ void gemm64_kernel(const float* __restrict__ X, const float* __restrict__ W,
                              const float* __restrict__ dinv,
                              const float* __restrict__ scale, const float* __restrict__ shift,
                              float* __restrict__ HP) {
    __shared__ float Ws[64 * 64];
    __shared__ float Xs[64 * 65];
    __shared__ float Ds[64];

    int tid  = threadIdx.x;
    int row0 = blockIdx.x * 64;

    float sc = 1.0f, sh = 0.0f;
    if (APPLY_BN) {   // input column is tid&63 for every sub-tile (stride 256 keeps low bits)
        sc = __ldg(scale + (tid & 63));
        sh = __ldg(shift + (tid & 63));
    }

#pragma unroll
    for (int j = 0; j < 16; j++) Ws[tid + j * 256] = W[tid + j * 256];
#pragma unroll
    for (int j = 0; j < 16; j++) {
        int idx = tid + j * 256;
        float v = X[(size_t)row0 * 64 + idx];
        if (APPLY_BN) v = fmaxf(fmaf(v, sc, sh), 0.0f);
        Xs[(idx >> 6) * 65 + (idx & 63)] = v;
    }
    if (tid < 64) Ds[tid] = dinv[row0 + tid];
    __syncthreads();

    int tx = tid & 63;
    int ty = tid >> 6;
    float acc[16];
#pragma unroll
    for (int i = 0; i < 16; i++) acc[i] = 0.0f;

#pragma unroll
    for (int k = 0; k < 64; k++) {
        float w = Ws[k * 64 + tx];
#pragma unroll
        for (int i = 0; i < 16; i++)
            acc[i] += Xs[(ty + 4 * i) * 65 + k] * w;
    }

#pragma unroll
    for (int i = 0; i < 16; i++) {
        int r = ty + 4 * i;
        HP[(size_t)(row0 + r) * 64 + tx] = acc[i] * Ds[r];
    }
}

// ---------------- CSR gather aggregation + fused BN stats ----------------
// agg[d] = dinv[d]*(h'[d] + sum h'[s]); block = 16 nodes x 16 float4-parts
__global__ void agg_kernel(const int* __restrict__ rowst, const int* __restrict__ cnt,
                           const int* __restrict__ adj, const float* __restrict__ dinv,
                           const float* __restrict__ HP, float* __restrict__ AGG,
                           double* __restrict__ psums) {
    int tid  = threadIdx.x;
    int node = blockIdx.x * 16 + (tid >> 4);
    int part = tid & 15;
    const float4* Hp = (const float4*)HP;

    float4 acc = __ldg(Hp + (size_t)node * 16 + part);   // self-loop h'[d]
    int beg = __ldg(rowst + node);
    int c   = __ldg(cnt + node);
    int j = 0;
    for (; j + 3 < c; j += 4) {
        int s0 = __ldg(adj + beg + j);
        int s1 = __ldg(adj + beg + j + 1);
        int s2 = __ldg(adj + beg + j + 2);
        int s3 = __ldg(adj + beg + j + 3);
        float4 a = __ldg(Hp + (size_t)s0 * 16 + part);
        float4 b = __ldg(Hp + (size_t)s1 * 16 + part);
        float4 d = __ldg(Hp + (size_t)s2 * 16 + part);
        float4 e = __ldg(Hp + (size_t)s3 * 16 + part);
        acc.x += (a.x + b.x) + (d.x + e.x);
        acc.y += (a.y + b.y) + (d.y + e.y);
        acc.z += (a.z + b.z) + (d.z + e.z);
        acc.w += (a.w + b.w) + (d.w + e.w);
    }
    for (; j < c; j++) {
        int s0 = __ldg(adj + beg + j);
        float4 a = __ldg(Hp + (size_t)s0 * 16 + part);
        acc.x += a.x; acc.y += a.y; acc.z += a.z; acc.w += a.w;
    }
    float dd = __ldg(dinv + node);
    acc.x *= dd; acc.y *= dd; acc.z *= dd; acc.w *= dd;
    ((float4*)AGG)[(size_t)node * 16 + part] = acc;

    // fused BN stats: block-reduce over 16 nodes, bucketed double atomics
    __shared__ float4 s_acc[256];
    s_acc[tid] = acc;
    __syncthreads();
    if (tid < 2 * HDIM) {   // tid < 128: first 64 = sum, next 64 = sumsq lanes share loads
        // thread f (0..63) computes sum & sumsq for feature f
        if (tid < HDIM) {
            const float* sa = (const float*)s_acc;
            float s = 0.0f, sq = 0.0f;
#pragma unroll
            for (int n = 0; n < 16; n++) {
                float v = sa[n * 64 + tid];
                s += v;
                sq += v * v;
            }
            int bucket = blockIdx.x & (NBUCKET - 1);
            atomicAdd(&psums[bucket * 128 + tid], (double)s);
            atomicAdd(&psums[bucket * 128 + HDIM + tid], (double)sq);
        }
    }
}

// ---------------- reduce stat buckets -> scale/shift ----------------
__global__ void bn_finalize_kernel(const double* __restrict__ psums,
                                   const float* __restrict__ g, const float* __restrict__ be,
                                   float* __restrict__ scale, float* __restrict__ shift) {
    int f = threadIdx.x;
    if (f >= HDIM) return;
    double s = 0.0, sq = 0.0;
#pragma unroll 4
    for (int b = 0; b < NBUCKET; b++) {
        s  += psums[b * 128 + f];
        sq += psums[b * 128 + HDIM + f];
    }
    double mean = s / (double)N_NODES;
    double var  = sq / (double)N_NODES - mean * mean;
    float rs = rsqrtf((float)var + BN_EPS);
    float sc = rs * g[f];
    scale[f] = sc;
    shift[f] = (float)(-mean) * sc + be[f];
}

// ---------------- fused: BN1+relu (recompute) + BN2+relu + residual + mean pool ----------------
__global__ void pool_fused_kernel(const float* __restrict__ AGG1, const float* __restrict__ AGG2,
                                  const float* __restrict__ scale, const float* __restrict__ shift,
                                  const int* __restrict__ batch, float* __restrict__ pooled) {
    int g = blockIdx.x;
    __shared__ int s_start, s_end;
    if (threadIdx.x == 0) {
        int lo = 0, hi = N_NODES;
        while (lo < hi) { int mid = (lo + hi) >> 1; if (batch[mid] < g) lo = mid + 1; else hi = mid; }
        s_start = lo;
        hi = N_NODES;
        while (lo < hi) { int mid = (lo + hi) >> 1; if (batch[mid] < g + 1) lo = mid + 1; else hi = mid; }
        s_end = lo;
    }
    __syncthreads();
    int start = s_start, end = s_end;
    int f = threadIdx.x & 63;
    int grp = threadIdx.x >> 6;
    float sc1 = __ldg(scale + f),        sh1 = __ldg(shift + f);
    float sc2 = __ldg(scale + HDIM + f), sh2 = __ldg(shift + HDIM + f);
    float s = 0.0f;
    for (int r = start + grp; r < end; r += 4) {
        float a1 = AGG1[(size_t)r * 64 + f];
        float a2 = AGG2[(size_t)r * 64 + f];
        s += fmaxf(fmaf(a1, sc1, sh1), 0.0f) + fmaxf(fmaf(a2, sc2, sh2), 0.0f);
    }
    __shared__ float shm[256];
    shm[threadIdx.x] = s;
    __syncthreads();
    if (grp == 0) {
        s = shm[f] + shm[f + 64] + shm[f + 128] + shm[f + 192];
        int cnt = end - start;
        pooled[g * 64 + f] = s / (float)(cnt > 0 ? cnt : 1);
    }
}

// ---------------- MLP head + log_softmax ----------------
__global__ void head_kernel(const float* __restrict__ pooled,
                            const float* __restrict__ lw1, const float* __restrict__ lb1,
                            const float* __restrict__ lw2, const float* __restrict__ lb2,
                            float* __restrict__ out) {
    int g = blockIdx.x;
    int t = threadIdx.x;
    __shared__ float p[64];
    __shared__ float z[32];
    __shared__ float lg[NCLS];
    p[t] = pooled[g * 64 + t];
    __syncthreads();
    if (t < 32) {
        float acc = lb1[t];
#pragma unroll
        for (int k = 0; k < 64; k++) acc += p[k] * lw1[k * 32 + t];
        z[t] = fmaxf(acc, 0.0f);
    }
    __syncthreads();
    if (t < NCLS) {
        float acc = lb2[t];
#pragma unroll
        for (int k = 0; k < 32; k++) acc += z[k] * lw2[k * 10 + t];
        lg[t] = acc;
    }
    __syncthreads();
    if (t == 0) {
        float m = lg[0];
#pragma unroll
        for (int c = 1; c < NCLS; c++) m = fmaxf(m, lg[c]);
        float se = 0.0f;
#pragma unroll
        for (int c = 0; c < NCLS; c++) se += expf(lg[c] - m);
        float l = m + logf(se);
#pragma unroll
        for (int c = 0; c < NCLS; c++) out[g * NCLS + c] = lg[c] - l;
    }
}

// ---------------- host ----------------
extern "C" void kernel_launch(void* const* d_in, const int* in_sizes, int n_in,
                              void* d_out, int out_size) {
    const float* x     = (const float*)d_in[0];
    const int*   ei    = (const int*)  d_in[1];
    const int*   batch = (const int*)  d_in[2];
    const float* W1  = (const float*)d_in[3];
    // b1 (d_in[4]) cancels inside BatchNorm
    const float* g1  = (const float*)d_in[5];
    const float* be1 = (const float*)d_in[6];
    const float* W2  = (const float*)d_in[7];
    // b2 (d_in[8]) cancels
    const float* g2  = (const float*)d_in[9];
    const float* be2 = (const float*)d_in[10];
    const float* lw1 = (const float*)d_in[11];
    const float* lb1 = (const float*)d_in[12];
    const float* lw2 = (const float*)d_in[13];
    const float* lb2 = (const float*)d_in[14];

    const int* src = ei;
    const int* dst = ei + N_EDGES;

    float *buf1, *buf2, *buf3, *dinv, *scale, *shift, *pooled;
    int *adj, *cnt, *rowst, *cursor, *localex, *blksum, *blkpre;
    double* psums;
    cudaGetSymbolAddress((void**)&buf1,   g_buf1);
    cudaGetSymbolAddress((void**)&buf2,   g_buf2);
    cudaGetSymbolAddress((void**)&buf3,   g_buf3);
    cudaGetSymbolAddress((void**)&adj,    g_adj);
    cudaGetSymbolAddress((void**)&cnt,    g_cnt);
    cudaGetSymbolAddress((void**)&rowst,  g_rowst);
    cudaGetSymbolAddress((void**)&cursor, g_cursor);
    cudaGetSymbolAddress((void**)&localex,g_localex);
    cudaGetSymbolAddress((void**)&blksum, g_blksum);
    cudaGetSymbolAddress((void**)&blkpre, g_blkpre);
    cudaGetSymbolAddress((void**)&dinv,   g_dinv);
    cudaGetSymbolAddress((void**)&psums,  g_psums);
    cudaGetSymbolAddress((void**)&scale,  g_scale);
    cudaGetSymbolAddress((void**)&shift,  g_shift);
    cudaGetSymbolAddress((void**)&pooled, g_pooled);

    const int TB = 256;
    const int n_blk    = (N_NODES + TB - 1) / TB;
    const int e_blk    = (N_EDGES + TB - 1) / TB;
    const int agg_blk  = N_NODES / 16;   // 12500 exact
    const int gemm_blk = N_NODES / 64;   // 3125 exact

    // ---- CSR build + norms ----
    init_kernel     <<<n_blk, TB>>>(cnt, psums);
    deg_count_kernel<<<e_blk, TB>>>(dst, cnt);
    scanA_kernel    <<<SCAN_BLKS, 256>>>(cnt, localex, blksum);
    scanB_kernel    <<<1, 256>>>(blksum, blkpre);
    scanC_kernel    <<<n_blk, TB>>>(localex, blkpre, cnt, rowst, cursor, dinv);
    scatter_kernel  <<<e_blk, TB>>>(src, dst, cursor, adj);

    // ---- layer 1 ----
    gemm64_kernel<false><<<gemm_blk, TB>>>(x, W1, dinv, nullptr, nullptr, buf1);
    agg_kernel          <<<agg_blk, TB>>>(rowst, cnt, adj, dinv, buf1, buf2, psums);
    bn_finalize_kernel  <<<1, 64>>>(psums, g1, be1, scale, shift);

    // ---- layer 2 (BN1+relu fused into gemm input load) ----
    gemm64_kernel<true> <<<gemm_blk, TB>>>(buf2, W2, dinv, scale, shift, buf1);
    agg_kernel          <<<agg_blk, TB>>>(rowst, cnt, adj, dinv, buf1, buf3, psums + PSUM_STRIDE);
    bn_finalize_kernel  <<<1, 64>>>(psums + PSUM_STRIDE, g2, be2, scale + HDIM, shift + HDIM);

    // ---- fused BN-apply(x2) + residual + pool, then head ----
    pool_fused_kernel<<<NGRAPH, TB>>>(buf2, buf3, scale, shift, batch, pooled);
    head_kernel<<<NGRAPH, 64>>>(pooled, lw1, lb1, lw2, lb2, (float*)d_out);
}

// round 8
// speedup vs baseline: 2.0032x; 1.6159x over previous
#include <cuda_runtime.h>
#include <math.h>

#define N_NODES 200000
#define N_EDGES 1000000
#define HDIM    64
#define NGRAPH  512
#define NCLS    10
#define BN_EPS  1e-5f

#define SCAN_CHUNK 1024
#define SCAN_BLKS  ((N_NODES + SCAN_CHUNK - 1) / SCAN_CHUNK)   // 196
#define NBUCKET 64
#define PSUM_STRIDE (NBUCKET * 2 * HDIM)   // 8192 doubles per layer

// ---------------- static device scratch ----------------
__device__ __align__(256) float  g_buf1[(size_t)N_NODES * HDIM]; // h' (gemm out)
__device__ __align__(256) float  g_buf2[(size_t)N_NODES * HDIM]; // AGG layer 1
__device__ __align__(256) float  g_buf3[(size_t)N_NODES * HDIM]; // AGG layer 2
__device__ __align__(256) int    g_adj[N_EDGES];
__device__ __align__(256) int    g_cnt[N_NODES];
__device__ __align__(256) int2   g_row2[N_NODES];                // {rowstart, cnt}
__device__ __align__(256) int    g_cursor[N_NODES];
__device__ __align__(256) int    g_localex[N_NODES];
__device__ __align__(16)  int    g_blksum[256];
__device__ __align__(256) float  g_dinv[N_NODES];
__device__ __align__(256) double g_psums[2 * PSUM_STRIDE];       // [layer][bucket][128]
__device__ __align__(16)  float  g_scale[HDIM];
__device__ __align__(16)  float  g_shift[HDIM];

// ---------------- init: zero counts + stat partials ----------------
__global__ void init_kernel(int* __restrict__ cnt, double* __restrict__ psums) {
    int i = blockIdx.x * blockDim.x + threadIdx.x;
    if (i < N_NODES) cnt[i] = 0;
    if (i < 2 * PSUM_STRIDE) psums[i] = 0.0;
}

__global__ void deg_count_kernel(const int* __restrict__ dst, int* __restrict__ cnt) {
    int e = blockIdx.x * blockDim.x + threadIdx.x;
    if (e < N_EDGES) atomicAdd(&cnt[dst[e]], 1);
}

// ---------------- scan over cnt (2 kernels: A computes block sums, C finishes) --------
__global__ void scanA_kernel(const int* __restrict__ cnt, int* __restrict__ localex,
                             int* __restrict__ blksum) {
    __shared__ int sh[256];
    int b = blockIdx.x, t = threadIdx.x;
    int base = b * SCAN_CHUNK + t * 4;
    int v0 = (base + 0 < N_NODES) ? cnt[base + 0] : 0;
    int v1 = (base + 1 < N_NODES) ? cnt[base + 1] : 0;
    int v2 = (base + 2 < N_NODES) ? cnt[base + 2] : 0;
    int v3 = (base + 3 < N_NODES) ? cnt[base + 3] : 0;
    int s = v0 + v1 + v2 + v3;
    sh[t] = s;
    __syncthreads();
#pragma unroll
    for (int off = 1; off < 256; off <<= 1) {
        int x = (t >= off) ? sh[t - off] : 0;
        __syncthreads();
        sh[t] += x;
        __syncthreads();
    }
    int excl = sh[t] - s;
    if (t == 255) blksum[b] = sh[255];
    if (base + 0 < N_NODES) localex[base + 0] = excl;  excl += v0;
    if (base + 1 < N_NODES) localex[base + 1] = excl;  excl += v1;
    if (base + 2 < N_NODES) localex[base + 2] = excl;  excl += v2;
    if (base + 3 < N_NODES) localex[base + 3] = excl;
}

// each block redundantly scans blksum (196 entries), then finalizes its 256 nodes
__global__ void scanC_kernel(const int* __restrict__ localex, const int* __restrict__ blksum,
                             const int* __restrict__ cnt,
                             int2* __restrict__ row2, int* __restrict__ cursor,
                             float* __restrict__ dinv) {
    __shared__ int sh[256];
    __shared__ int pre[256];
    int t = threadIdx.x;
    int v = (t < SCAN_BLKS) ? blksum[t] : 0;
    sh[t] = v;
    __syncthreads();
#pragma unroll
    for (int off = 1; off < 256; off <<= 1) {
        int x = (t >= off) ? sh[t - off] : 0;
        __syncthreads();
        sh[t] += x;
        __syncthreads();
    }
    pre[t] = sh[t] - v;   // exclusive prefix of block sums
    __syncthreads();

    int i = blockIdx.x * 256 + t;
    if (i < N_NODES) {
        int c = cnt[i];
        int r = localex[i] + pre[i >> 10];
        row2[i] = make_int2(r, c);
        cursor[i] = r;
        dinv[i] = rsqrtf((float)(c + 1));
    }
}

__global__ void scatter_kernel(const int* __restrict__ src, const int* __restrict__ dst,
                               int* __restrict__ cursor, int* __restrict__ adj) {
    int e = blockIdx.x * blockDim.x + threadIdx.x;
    if (e >= N_EDGES) return;
    int d = dst[e];
    int pos = atomicAdd(&cursor[d], 1);
    adj[pos] = src[e];
}

// ---------------- 64x64 GEMM, 4x4 register tiles, float4 SMEM ----------------
// 256 threads = 16x16; thread (tr,tc) computes rows 4tr..+3, cols 4tc..+3.
template <bool APPLY_BN>
__global__ void __launch_bounds__(256) gemm64_kernel(
        const float* __restrict__ X, const float* __restrict__ W,
        const float* __restrict__ dinv,
        const float* __restrict__ scale, const float* __restrict__ shift,
        float* __restrict__ HP) {
    __shared__ __align__(16) float Ws[64 * 64];   // [k][col]
    __shared__ __align__(16) float Xt[64 * 68];   // [k][row], stride 68 (16B-aligned rows)
    __shared__ float Ds[64];

    int tid  = threadIdx.x;
    int row0 = blockIdx.x * 64;

    float sc = 1.0f, sh = 0.0f;
    if (APPLY_BN) {
        sc = __ldg(scale + (tid & 63));
        sh = __ldg(shift + (tid & 63));
    }

#pragma unroll
    for (int j = 0; j < 16; j++) Ws[tid + j * 256] = W[tid + j * 256];
#pragma unroll
    for (int j = 0; j < 16; j++) {
        int idx = tid + j * 256;
        int r = idx >> 6, c = idx & 63;
        float v = X[(size_t)row0 * 64 + idx];
        if (APPLY_BN) v = fmaxf(fmaf(v, sc, sh), 0.0f);
        Xt[c * 68 + r] = v;   // transpose: Xt[k][row]
    }
    if (tid < 64) Ds[tid] = dinv[row0 + tid];
    __syncthreads();

    int tr = tid >> 4, tc = tid & 15;
    float acc[4][4];
#pragma unroll
    for (int i = 0; i < 4; i++)
#pragma unroll
        for (int j = 0; j < 4; j++) acc[i][j] = 0.0f;

#pragma unroll
    for (int k = 0; k < 64; k++) {
        float4 xv = *(const float4*)&Xt[k * 68 + 4 * tr];
        float4 wv = *(const float4*)&Ws[k * 64 + 4 * tc];
        acc[0][0] += xv.x * wv.x; acc[0][1] += xv.x * wv.y; acc[0][2] += xv.x * wv.z; acc[0][3] += xv.x * wv.w;
        acc[1][0] += xv.y * wv.x; acc[1][1] += xv.y * wv.y; acc[1][2] += xv.y * wv.z; acc[1][3] += xv.y * wv.w;
        acc[2][0] += xv.z * wv.x; acc[2][1] += xv.z * wv.y; acc[2][2] += xv.z * wv.z; acc[2][3] += xv.z * wv.w;
        acc[3][0] += xv.w * wv.x; acc[3][1] += xv.w * wv.y; acc[3][2] += xv.w * wv.z; acc[3][3] += xv.w * wv.w;
    }

#pragma unroll
    for (int i = 0; i < 4; i++) {
        int r = 4 * tr + i;
        float d = Ds[r];
        float4 o;
        o.x = acc[i][0] * d; o.y = acc[i][1] * d;
        o.z = acc[i][2] * d; o.w = acc[i][3] * d;
        *(float4*)&HP[(size_t)(row0 + r) * 64 + 4 * tc] = o;
    }
}

// ---------------- CSR gather aggregation + fused BN stats ----------------
__global__ void __launch_bounds__(256) agg_kernel(
        const int2* __restrict__ row2, const int* __restrict__ adj,
        const float* __restrict__ dinv,
        const float* __restrict__ HP, float* __restrict__ AGG,
        double* __restrict__ psums) {
    int tid  = threadIdx.x;
    int node = blockIdx.x * 16 + (tid >> 4);
    int part = tid & 15;
    const float4* Hp = (const float4*)HP;

    float4 acc = __ldg(Hp + (size_t)node * 16 + part);   // self-loop h'[d]
    int2 rc = __ldg(row2 + node);
    int beg = rc.x, c = rc.y;
    int j = 0;
    for (; j + 3 < c; j += 4) {
        int s0 = __ldg(adj + beg + j);
        int s1 = __ldg(adj + beg + j + 1);
        int s2 = __ldg(adj + beg + j + 2);
        int s3 = __ldg(adj + beg + j + 3);
        float4 a = __ldg(Hp + (size_t)s0 * 16 + part);
        float4 b = __ldg(Hp + (size_t)s1 * 16 + part);
        float4 d = __ldg(Hp + (size_t)s2 * 16 + part);
        float4 e = __ldg(Hp + (size_t)s3 * 16 + part);
        acc.x += (a.x + b.x) + (d.x + e.x);
        acc.y += (a.y + b.y) + (d.y + e.y);
        acc.z += (a.z + b.z) + (d.z + e.z);
        acc.w += (a.w + b.w) + (d.w + e.w);
    }
    for (; j < c; j++) {
        int s0 = __ldg(adj + beg + j);
        float4 a = __ldg(Hp + (size_t)s0 * 16 + part);
        acc.x += a.x; acc.y += a.y; acc.z += a.z; acc.w += a.w;
    }
    float dd = __ldg(dinv + node);
    acc.x *= dd; acc.y *= dd; acc.z *= dd; acc.w *= dd;
    ((float4*)AGG)[(size_t)node * 16 + part] = acc;

    // fused BN stats: block-reduce over 16 nodes, bucketed double atomics
    __shared__ float4 s_acc[256];
    s_acc[tid] = acc;
    __syncthreads();
    if (tid < HDIM) {
        const float* sa = (const float*)s_acc;
        float s = 0.0f, sq = 0.0f;
#pragma unroll
        for (int n = 0; n < 16; n++) {
            float v = sa[n * 64 + tid];
            s += v;
            sq += v * v;
        }
        int bucket = blockIdx.x & (NBUCKET - 1);
        atomicAdd(&psums[bucket * 128 + tid], (double)s);
        atomicAdd(&psums[bucket * 128 + HDIM + tid], (double)sq);
    }
}

// ---------------- layer-1 BN finalize (needed before gemm2) ----------------
__global__ void bn_finalize_kernel(const double* __restrict__ psums,
                                   const float* __restrict__ g, const float* __restrict__ be,
                                   float* __restrict__ scale, float* __restrict__ shift) {
    int f = threadIdx.x;
    if (f >= HDIM) return;
    double s = 0.0, sq = 0.0;
#pragma unroll 4
    for (int b = 0; b < NBUCKET; b++) {
        s  += psums[b * 128 + f];
        sq += psums[b * 128 + HDIM + f];
    }
    double mean = s / (double)N_NODES;
    double var  = sq / (double)N_NODES - mean * mean;
    float rs = rsqrtf((float)var + BN_EPS);
    float sc = rs * g[f];
    scale[f] = sc;
    shift[f] = (float)(-mean) * sc + be[f];
}

// ---------------- fused: BN2-finalize + BN1/BN2 apply + residual + pool + MLP head ----
__global__ void __launch_bounds__(512) poolhead_kernel(
        const float* __restrict__ AGG1, const float* __restrict__ AGG2,
        const float* __restrict__ scale1, const float* __restrict__ shift1,
        const double* __restrict__ psums2,
        const float* __restrict__ g2, const float* __restrict__ be2,
        const int* __restrict__ batch,
        const float* __restrict__ lw1, const float* __restrict__ lb1,
        const float* __restrict__ lw2, const float* __restrict__ lb2,
        float* __restrict__ out) {
    int g = blockIdx.x;
    int tid = threadIdx.x;

    __shared__ float sc2s[64], sh2s[64];
    __shared__ int s_start, s_end;

    // threads [64,128): BN2 finalize; thread 0: binary-search graph bounds (parallel)
    if (tid >= 64 && tid < 128) {
        int f = tid - 64;
        double s = 0.0, sq = 0.0;
#pragma unroll 4
        for (int b = 0; b < NBUCKET; b++) {
            s  += psums2[b * 128 + f];
            sq += psums2[b * 128 + HDIM + f];
        }
        double mean = s / (double)N_NODES;
        double var  = sq / (double)N_NODES - mean * mean;
        float rs = rsqrtf((float)var + BN_EPS);
        float sc = rs * g2[f];
        sc2s[f] = sc;
        sh2s[f] = (float)(-mean) * sc + be2[f];
    }
    if (tid == 0) {
        int lo = 0, hi = N_NODES;
        while (lo < hi) { int mid = (lo + hi) >> 1; if (batch[mid] < g) lo = mid + 1; else hi = mid; }
        s_start = lo;
        hi = N_NODES;
        while (lo < hi) { int mid = (lo + hi) >> 1; if (batch[mid] < g + 1) lo = mid + 1; else hi = mid; }
        s_end = lo;
    }
    __syncthreads();

    int start = s_start, end = s_end;
    int f = tid & 63;
    int grp = tid >> 6;   // 0..7
    float sc1 = __ldg(scale1 + f), sh1 = __ldg(shift1 + f);
    float sc2 = sc2s[f],           sh2 = sh2s[f];
    float s = 0.0f;
#pragma unroll 2
    for (int r = start + grp; r < end; r += 8) {
        float a1 = AGG1[(size_t)r * 64 + f];
        float a2 = AGG2[(size_t)r * 64 + f];
        s += fmaxf(fmaf(a1, sc1, sh1), 0.0f) + fmaxf(fmaf(a2, sc2, sh2), 0.0f);
    }
    __shared__ float shm[512];
    shm[tid] = s;
    __syncthreads();

    __shared__ float p[64];
    if (grp == 0) {
        float t = 0.0f;
#pragma unroll
        for (int q = 0; q < 8; q++) t += shm[f + q * 64];
        int cnt = end - start;
        p[f] = t / (float)(cnt > 0 ? cnt : 1);
    }
    __syncthreads();

    // MLP head + log_softmax, all in SMEM
    __shared__ float z[32];
    __shared__ float lg[NCLS];
    if (tid < 32) {
        float acc = lb1[tid];
#pragma unroll
        for (int k = 0; k < 64; k++) acc += p[k] * lw1[k * 32 + tid];
        z[tid] = fmaxf(acc, 0.0f);
    }
    __syncthreads();
    if (tid < NCLS) {
        float acc = lb2[tid];
#pragma unroll
        for (int k = 0; k < 32; k++) acc += z[k] * lw2[k * 10 + tid];
        lg[tid] = acc;
    }
    __syncthreads();
    if (tid == 0) {
        float m = lg[0];
#pragma unroll
        for (int c = 1; c < NCLS; c++) m = fmaxf(m, lg[c]);
        float se = 0.0f;
#pragma unroll
        for (int c = 0; c < NCLS; c++) se += expf(lg[c] - m);
        float l = m + logf(se);
#pragma unroll
        for (int c = 0; c < NCLS; c++) out[g * NCLS + c] = lg[c] - l;
    }
}

// ---------------- host ----------------
extern "C" void kernel_launch(void* const* d_in, const int* in_sizes, int n_in,
                              void* d_out, int out_size) {
    const float* x     = (const float*)d_in[0];
    const int*   ei    = (const int*)  d_in[1];
    const int*   batch = (const int*)  d_in[2];
    const float* W1  = (const float*)d_in[3];
    // b1 (d_in[4]) cancels inside BatchNorm
    const float* g1  = (const float*)d_in[5];
    const float* be1 = (const float*)d_in[6];
    const float* W2  = (const float*)d_in[7];
    // b2 (d_in[8]) cancels
    const float* g2  = (const float*)d_in[9];
    const float* be2 = (const float*)d_in[10];
    const float* lw1 = (const float*)d_in[11];
    const float* lb1 = (const float*)d_in[12];
    const float* lw2 = (const float*)d_in[13];
    const float* lb2 = (const float*)d_in[14];

    const int* src = ei;
    const int* dst = ei + N_EDGES;

    float *buf1, *buf2, *buf3, *dinv, *scale, *shift;
    int *adj, *cnt, *cursor, *localex, *blksum;
    int2* row2;
    double* psums;
    cudaGetSymbolAddress((void**)&buf1,   g_buf1);
    cudaGetSymbolAddress((void**)&buf2,   g_buf2);
    cudaGetSymbolAddress((void**)&buf3,   g_buf3);
    cudaGetSymbolAddress((void**)&adj,    g_adj);
    cudaGetSymbolAddress((void**)&cnt,    g_cnt);
    cudaGetSymbolAddress((void**)&row2,   g_row2);
    cudaGetSymbolAddress((void**)&cursor, g_cursor);
    cudaGetSymbolAddress((void**)&localex,g_localex);
    cudaGetSymbolAddress((void**)&blksum, g_blksum);
    cudaGetSymbolAddress((void**)&dinv,   g_dinv);
    cudaGetSymbolAddress((void**)&psums,  g_psums);
    cudaGetSymbolAddress((void**)&scale,  g_scale);
    cudaGetSymbolAddress((void**)&shift,  g_shift);

    const int TB = 256;
    const int n_blk    = (N_NODES + TB - 1) / TB;   // 782
    const int e_blk    = (N_EDGES + TB - 1) / TB;
    const int agg_blk  = N_NODES / 16;              // 12500 exact
    const int gemm_blk = N_NODES / 64;              // 3125 exact

    // ---- CSR build + norms ----
    init_kernel     <<<n_blk, TB>>>(cnt, psums);
    deg_count_kernel<<<e_blk, TB>>>(dst, cnt);
    scanA_kernel    <<<SCAN_BLKS, 256>>>(cnt, localex, blksum);
    scanC_kernel    <<<n_blk, 256>>>(localex, blksum, cnt, row2, cursor, dinv);
    scatter_kernel  <<<e_blk, TB>>>(src, dst, cursor, adj);

    // ---- layer 1 ----
    gemm64_kernel<false><<<gemm_blk, TB>>>(x, W1, dinv, nullptr, nullptr, buf1);
    agg_kernel          <<<agg_blk, TB>>>(row2, adj, dinv, buf1, buf2, psums);
    bn_finalize_kernel  <<<1, 64>>>(psums, g1, be1, scale, shift);

    // ---- layer 2 (BN1+relu fused into gemm input load) ----
    gemm64_kernel<true> <<<gemm_blk, TB>>>(buf2, W2, dinv, scale, shift, buf1);
    agg_kernel          <<<agg_blk, TB>>>(row2, adj, dinv, buf1, buf3, psums + PSUM_STRIDE);

    // ---- fused BN2-finalize + BN-apply(x2) + residual + pool + head ----
    poolhead_kernel<<<NGRAPH, 512>>>(buf2, buf3, scale, shift, psums + PSUM_STRIDE,
                                     g2, be2, batch, lw1, lb1, lw2, lb2, (float*)d_out);
}